// round 14
// baseline (speedup 1.0000x reference)
#include <cuda_runtime.h>
#include <cuda_bf16.h>
#include <cstdint>

// ---------------------------------------------------------------------------
// Problem constants
// ---------------------------------------------------------------------------
#define EMBED   256
#define NHEADS  8
#define BATCH   4
#define NQ      5440
#define NV      5440
#define MROWS   (BATCH * NQ)   // 21760 = 170 * 128
#define KSPLIT  512            // [hi(256) | lo(256)] bf16

// ---------------------------------------------------------------------------
// Scratch (device globals; no allocation allowed)
// ---------------------------------------------------------------------------
#define VPAD    (66 * EMBED)
__device__ float g_vbuf[(size_t)VPAD + (size_t)MROWS * EMBED + (size_t)VPAD];
__device__ float g_off[(size_t)MROWS * EMBED];
__device__ float g_aw [(size_t)MROWS * 128];

__device__ __nv_bfloat16 g_Av [(size_t)MROWS * KSPLIT];  // value  split
__device__ __nv_bfloat16 g_Aq [(size_t)MROWS * KSPLIT];  // query  split
__device__ __nv_bfloat16 g_Aat[(size_t)MROWS * KSPLIT];  // attn-out split (from msda)
__device__ __nv_bfloat16 g_Bv  [256 * KSPLIT];           // weights split (K-major)
__device__ __nv_bfloat16 g_Bo  [256 * KSPLIT];
__device__ __nv_bfloat16 g_Ba  [128 * KSPLIT];
__device__ __nv_bfloat16 g_Bout[256 * KSPLIT];

// ---------------------------------------------------------------------------
// PTX helpers (baseline compute_103-safe)
// ---------------------------------------------------------------------------
__device__ __forceinline__ uint32_t smem_u32(const void* p) {
    uint32_t a;
    asm("{ .reg .u64 t; cvta.to.shared.u64 t, %1; cvt.u32.u64 %0, t; }"
        : "=r"(a) : "l"(p));
    return a;
}
__device__ __forceinline__ void cp_async16(uint32_t dst, const void* src) {
    asm volatile("cp.async.cg.shared.global [%0], [%1], 16;"
                 :: "r"(dst), "l"(src) : "memory");
}
__device__ __forceinline__ void cp_commit() {
    asm volatile("cp.async.commit_group;" ::: "memory");
}
template <int N>
__device__ __forceinline__ void cp_wait() {
    asm volatile("cp.async.wait_group %0;" :: "n"(N) : "memory");
}
__device__ __forceinline__ void ldsm_x4(uint32_t& r0, uint32_t& r1,
                                        uint32_t& r2, uint32_t& r3, uint32_t a) {
    asm volatile("ldmatrix.sync.aligned.m8n8.x4.shared.b16 {%0,%1,%2,%3}, [%4];"
                 : "=r"(r0), "=r"(r1), "=r"(r2), "=r"(r3) : "r"(a));
}
__device__ __forceinline__ void mma16816(float* d, const uint32_t* a,
                                         uint32_t b0, uint32_t b1) {
    asm volatile(
        "mma.sync.aligned.m16n8k16.row.col.f32.bf16.bf16.f32 "
        "{%0,%1,%2,%3}, {%4,%5,%6,%7}, {%8,%9}, {%0,%1,%2,%3};"
        : "+f"(d[0]), "+f"(d[1]), "+f"(d[2]), "+f"(d[3])
        : "r"(a[0]), "r"(a[1]), "r"(a[2]), "r"(a[3]), "r"(b0), "r"(b1));
}

// ---------------------------------------------------------------------------
// Fused fp32 -> split-bf16 conversion (activations + all 4 weight matrices)
// ---------------------------------------------------------------------------
__device__ __forceinline__ void conv_act_body(
    const float* __restrict__ in, __nv_bfloat16* __restrict__ out, int i)
{
    int r = i >> 6, k4 = (i & 63) << 2;
    float4 x = *(const float4*)(in + (size_t)r * 256 + k4);
    alignas(8) __nv_bfloat16 h[4], l[4];
    h[0] = __float2bfloat16(x.x); l[0] = __float2bfloat16(x.x - __bfloat162float(h[0]));
    h[1] = __float2bfloat16(x.y); l[1] = __float2bfloat16(x.y - __bfloat162float(h[1]));
    h[2] = __float2bfloat16(x.z); l[2] = __float2bfloat16(x.z - __bfloat162float(h[2]));
    h[3] = __float2bfloat16(x.w); l[3] = __float2bfloat16(x.w - __bfloat162float(h[3]));
    *(uint2*)(out + (size_t)r * KSPLIT + k4)       = *(uint2*)h;
    *(uint2*)(out + (size_t)r * KSPLIT + 256 + k4) = *(uint2*)l;
}
__device__ __forceinline__ void conv_wt_body(
    const float* __restrict__ W, __nv_bfloat16* __restrict__ out, int N, int i)
{
    int n = i >> 8, k = i & 255;
    float x = W[(size_t)k * N + n];
    __nv_bfloat16 h = __float2bfloat16(x);
    out[(size_t)n * KSPLIT + k]       = h;
    out[(size_t)n * KSPLIT + 256 + k] = __float2bfloat16(x - __bfloat162float(h));
}

// grid segments: [0,5440) value, [5440,10880) query,
// [10880,11136) Wv, [11136,11392) Wo, [11392,11520) Wa, [11520,11776) Wout
__global__ __launch_bounds__(256) void conv_all(
    const float* __restrict__ value, const float* __restrict__ query,
    const float* __restrict__ Wv, const float* __restrict__ Wo,
    const float* __restrict__ Wa, const float* __restrict__ Wout,
    __nv_bfloat16* __restrict__ Av, __nv_bfloat16* __restrict__ Aq,
    __nv_bfloat16* __restrict__ Bv, __nv_bfloat16* __restrict__ Bo,
    __nv_bfloat16* __restrict__ Ba, __nv_bfloat16* __restrict__ Bout)
{
    const int id = blockIdx.x, tid = threadIdx.x;
    if (id < 5440) {
        conv_act_body(value, Av, id * 256 + tid);
    } else if (id < 10880) {
        conv_act_body(query, Aq, (id - 5440) * 256 + tid);
    } else if (id < 11136) {
        conv_wt_body(Wv, Bv, 256, (id - 10880) * 256 + tid);
    } else if (id < 11392) {
        conv_wt_body(Wo, Bo, 256, (id - 11136) * 256 + tid);
    } else if (id < 11520) {
        conv_wt_body(Wa, Ba, 128, (id - 11392) * 256 + tid);
    } else {
        conv_wt_body(Wout, Bout, 256, (id - 11520) * 256 + tid);
    }
}

// ---------------------------------------------------------------------------
// HMMA GEMM body v5: R11 config (CTA 128x128, 8 warps @ 64x32, 3-stage ring)
// + WARP-STAGGERED ks ORDER. Each warp walks the 4 ks-slices rotated by its
// warp id, so at any instant ~half the warps are in ldsm and half in mma —
// breaking the barrier-induced phase-lock that made the shared-crossbar and
// tensor pipes run additively (2537 cyc/chunk ≈ LDS 1536 + HMMA 1024).
// ---------------------------------------------------------------------------
#define NCHUNK 12
#define STG    32768                 // A(16K) + B(16K) per stage
#define GSMEM  (3 * STG)             // 96 KB

__device__ __forceinline__ void gemm_body(
    const __nv_bfloat16* __restrict__ A, const __nv_bfloat16* __restrict__ B,
    const float* __restrict__ bias, float* __restrict__ C, int N,
    int r0, int c0, char* smem)
{
    const uint32_t sb = smem_u32(smem);
    const int tid = threadIdx.x, wid = tid >> 5, lane = tid & 31;
    const int warp_m = wid & 1, warp_n = wid >> 1;   // 2 x 4 warp grid

    const int cpRow = tid >> 1;          // 0..127
    const int cpU0  = (tid & 1) * 4;     // 0 or 4 (16B units)

    auto prefetch = [&](int c, int st) {
        const int p  = c >> 2, kc = c & 3;
        const int ka = ((p == 1) ? 256 : 0) + kc * 64;
        const int kb = ((p == 2) ? 256 : 0) + kc * 64;
        const __nv_bfloat16* ga = A + (size_t)(r0 + cpRow) * KSPLIT + ka + cpU0 * 8;
        const __nv_bfloat16* gb = B + (size_t)(c0 + cpRow) * KSPLIT + kb + cpU0 * 8;
        const uint32_t sa = sb + st * STG + cpRow * 128;
        const uint32_t sg = sa + 16384;
        const int swz = cpRow & 7;
#pragma unroll
        for (int i = 0; i < 4; i++) {
            const int u = cpU0 + i;
            cp_async16(sa + ((u ^ swz) << 4), ga + i * 8);
            cp_async16(sg + ((u ^ swz) << 4), gb + i * 8);
        }
        cp_commit();
    };

    const int r7   = lane & 7;
    const int arow = (lane & 7) | (((lane >> 3) & 1) << 3);
    const int ah   = (lane >> 4) & 1;
    const int brow = (lane & 7) | (((lane >> 4) & 1) << 3);
    const int bh   = (lane >> 3) & 1;

    float acc[4][4][4];
#pragma unroll
    for (int mi = 0; mi < 4; mi++)
#pragma unroll
        for (int ni = 0; ni < 4; ni++)
#pragma unroll
            for (int j = 0; j < 4; j++) acc[mi][ni][j] = 0.f;

    prefetch(0, 0);
    prefetch(1, 1);

    for (int c = 0; c < NCHUNK; c++) {
        if (c + 1 < NCHUNK) cp_wait<1>(); else cp_wait<0>();
        __syncthreads();
        if (c + 2 < NCHUNK) prefetch(c + 2, (c + 2) % 3);

        const uint32_t Ast = sb + (c % 3) * STG;
        const uint32_t Bst = Ast + 16384;

#pragma unroll
        for (int ksi = 0; ksi < 4; ksi++) {
            const int ks = (ksi + wid) & 3;          // warp-staggered order
            uint32_t af[4][4];
#pragma unroll
            for (int mi = 0; mi < 4; mi++) {
                const int row = warp_m * 64 + mi * 16 + arow;
                const uint32_t addr = Ast + row * 128 + (((ks * 2 + ah) ^ r7) << 4);
                ldsm_x4(af[mi][0], af[mi][1], af[mi][2], af[mi][3], addr);
            }
            uint32_t bf[4][2];
#pragma unroll
            for (int nh = 0; nh < 2; nh++) {
                const int row = warp_n * 32 + nh * 16 + brow;
                const uint32_t addr = Bst + row * 128 + (((ks * 2 + bh) ^ r7) << 4);
                uint32_t t0, t1, t2, t3;
                ldsm_x4(t0, t1, t2, t3, addr);
                bf[nh * 2][0] = t0; bf[nh * 2][1] = t1;
                bf[nh * 2 + 1][0] = t2; bf[nh * 2 + 1][1] = t3;
            }
#pragma unroll
            for (int mi = 0; mi < 4; mi++)
#pragma unroll
                for (int ni = 0; ni < 4; ni++)
                    mma16816(acc[mi][ni], af[mi], bf[ni][0], bf[ni][1]);
        }
    }

    // epilogue: bias + store
    const int g = lane >> 2, tig = lane & 3;
    float2 bb[4];
#pragma unroll
    for (int ni = 0; ni < 4; ni++)
        bb[ni] = *(const float2*)(bias + c0 + warp_n * 32 + ni * 8 + tig * 2);
#pragma unroll
    for (int mi = 0; mi < 4; mi++) {
        const int rowg = r0 + warp_m * 64 + mi * 16 + g;
        float* p0 = C + (size_t)rowg * N + c0 + warp_n * 32 + tig * 2;
        float* p1 = p0 + (size_t)8 * N;
#pragma unroll
        for (int ni = 0; ni < 4; ni++) {
            float2 o0 = { acc[mi][ni][0] + bb[ni].x, acc[mi][ni][1] + bb[ni].y };
            float2 o1 = { acc[mi][ni][2] + bb[ni].x, acc[mi][ni][3] + bb[ni].y };
            *(float2*)(p0 + ni * 8) = o0;
            *(float2*)(p1 + ni * 8) = o1;
        }
    }
}

// Fused: seg0 value-proj (340 CTAs), seg1 offsets (340), seg2 logits (170)
__global__ __launch_bounds__(256, 2) void gemm_fused3(
    const __nv_bfloat16* __restrict__ Av, const __nv_bfloat16* __restrict__ Aq,
    const __nv_bfloat16* __restrict__ Bv, const __nv_bfloat16* __restrict__ Bo,
    const __nv_bfloat16* __restrict__ Ba,
    const float* __restrict__ bv, const float* __restrict__ bo,
    const float* __restrict__ ba,
    float* __restrict__ Cv, float* __restrict__ Co, float* __restrict__ Ca)
{
    extern __shared__ char smem[];
    int id = blockIdx.x;
    if (id < 340) {
        gemm_body(Av, Bv, bv, Cv, 256, (id >> 1) * 128, (id & 1) * 128, smem);
    } else if (id < 680) {
        id -= 340;
        gemm_body(Aq, Bo, bo, Co, 256, (id >> 1) * 128, (id & 1) * 128, smem);
    } else {
        id -= 680;
        gemm_body(Aq, Ba, ba, Ca, 128, id * 128, 0, smem);
    }
}

__global__ __launch_bounds__(256, 2) void gemm_out(
    const __nv_bfloat16* __restrict__ A, const __nv_bfloat16* __restrict__ B,
    const float* __restrict__ bias, float* __restrict__ C)
{
    extern __shared__ char smem[];
    gemm_body(A, B, bias, C, 256, (blockIdx.x >> 1) * 128, (blockIdx.x & 1) * 128, smem);
}

// ---------------------------------------------------------------------------
// Deformable sampling v4 (unchanged from R13): one warp per (b, q, head-pair).
// ---------------------------------------------------------------------------
__global__ __launch_bounds__(256) void msda_sample(
    const float* __restrict__ v, const float* __restrict__ off,
    const float* __restrict__ aw, const float* __restrict__ ref,
    __nv_bfloat16* __restrict__ outs)   // (B*NQ, 512) = [hi|lo]
{
    const int wid  = threadIdx.x >> 5;            // 0..7
    const int lane = threadIdx.x & 31;
    const int bq   = blockIdx.x * 2 + (wid >> 2); // 2 queries per block
    const int hp   = wid & 3;                     // head pair 0..3
    const int b    = bq / NQ;
    const unsigned FULL = 0xffffffffu;

    const int head_sel = lane >> 4;               // 0 or 1
    const int j        = lane & 15;               // point index within head

    // ---- softmax over 16 logits, both heads at once (width-16 lanes) ----
    const float a = aw[((size_t)bq * NHEADS + hp * 2) * 16 + lane];
    float m = a;
#pragma unroll
    for (int o = 8; o; o >>= 1) m = fmaxf(m, __shfl_xor_sync(FULL, m, o));
    const float e = expf(a - m);
    float s = e;
#pragma unroll
    for (int o = 8; o; o >>= 1) s += __shfl_xor_sync(FULL, s, o);
    const float p = e / s;    // prob of this lane's point

    // ---- phase 1: every lane computes its point's base offset + weights ----
    const float* offp = off + (size_t)bq * EMBED + hp * 64;
    const float offv0 = offp[lane];          // head 2hp   : pts 0-15 (x,y)
    const float offv1 = offp[32 + lane];     // head 2hp+1 : pts 0-15 (x,y)
    const float oxA = __shfl_sync(FULL, offv0, 2 * j);
    const float oyA = __shfl_sync(FULL, offv0, 2 * j + 1);
    const float oxB = __shfl_sync(FULL, offv1, 2 * j);
    const float oyB = __shfl_sync(FULL, offv1, 2 * j + 1);
    const float ox = head_sel ? oxB : oxA;
    const float oy = head_sel ? oyB : oyA;

    const float refv = (lane < 8) ? ref[(size_t)bq * 8 + lane] : 0.f;
    const int   l  = (j >> 2) & 3;                // level of this point
    const float rx = __shfl_sync(FULL, refv, 2 * l);
    const float ry = __shfl_sync(FULL, refv, 2 * l + 1);

    const int   Wi  = 64 >> l;
    const float Wf  = (float)Wi;
    const int   cur = (16384 - (16384 >> (2 * l))) / 3;

    const float px = (rx + ox / Wf) * Wf - 0.5f;
    const float py = (ry + oy / Wf) * Wf - 0.5f;
    const float x0f = floorf(px), y0f = floorf(py);
    const float wx = px - x0f,    wy = py - y0f;
    const int x0 = (int)x0f, y0 = (int)y0f;

    const bool vx0 = (x0 >= 0)  & (x0 < Wi);
    const bool vx1 = (x0 >= -1) & (x0 < Wi - 1);
    const bool vy0 = (y0 >= 0)  & (y0 < Wi);
    const bool vy1 = (y0 >= -1) & (y0 < Wi - 1);
    const float u = 1.f - wx, t = 1.f - wy;

    float c00 = (vx0 && vy0) ? p * u  * t  : 0.f;
    float c10 = (vx1 && vy0) ? p * wx * t  : 0.f;
    float c01 = (vx0 && vy1) ? p * u  * wy : 0.f;
    float c11 = (vx1 && vy1) ? p * wx * wy : 0.f;

    int idx = cur + y0 * Wi + x0;
    idx = min(max(idx, -65), NV - 1);
    const int o00 = idx << 10;

    // ---- phase 2: 8 iterations; this lane gathers point (it*2 + slot) of
    //      head (2hp + head_sel), channel quad c4 ----
    const int slot = (lane >> 3) & 1;
    const int c4   = lane & 7;
    const int myhead = hp * 2 + head_sel;
    const char* vb = (const char*)(v + (size_t)b * NV * EMBED + myhead * 32 + c4 * 4);
    const int srcbase = head_sel * 16 + slot;     // shfl source lane base

    float a0 = 0.f, a1 = 0.f, a2 = 0.f, a3 = 0.f;
#pragma unroll
    for (int it = 0; it < 8; it++) {
        const int rowB = (64 >> (it >> 1)) << 10;   // level = it>>1 (uniform)
        const int src  = srcbase + it * 2;          // point j = it*2 + slot
        const int   io  = __shfl_sync(FULL, o00, src);
        const float w00 = __shfl_sync(FULL, c00, src);
        const float w10 = __shfl_sync(FULL, c10, src);
        const float w01 = __shfl_sync(FULL, c01, src);
        const float w11 = __shfl_sync(FULL, c11, src);
        const char* ad = vb + io;
        const float4 v00 = *(const float4*)(ad);
        const float4 v10 = *(const float4*)(ad + 1024);
        const float4 v01 = *(const float4*)(ad + rowB);
        const float4 v11 = *(const float4*)(ad + rowB + 1024);
        a0 = fmaf(w00, v00.x, a0); a1 = fmaf(w00, v00.y, a1);
        a2 = fmaf(w00, v00.z, a2); a3 = fmaf(w00, v00.w, a3);
        a0 = fmaf(w10, v10.x, a0); a1 = fmaf(w10, v10.y, a1);
        a2 = fmaf(w10, v10.z, a2); a3 = fmaf(w10, v10.w, a3);
        a0 = fmaf(w01, v01.x, a0); a1 = fmaf(w01, v01.y, a1);
        a2 = fmaf(w01, v01.z, a2); a3 = fmaf(w01, v01.w, a3);
        a0 = fmaf(w11, v11.x, a0); a1 = fmaf(w11, v11.y, a1);
        a2 = fmaf(w11, v11.z, a2); a3 = fmaf(w11, v11.w, a3);
    }
    // combine the two point slots of this head (lane bit 3)
    a0 += __shfl_xor_sync(FULL, a0, 8);  a1 += __shfl_xor_sync(FULL, a1, 8);
    a2 += __shfl_xor_sync(FULL, a2, 8);  a3 += __shfl_xor_sync(FULL, a3, 8);

    // ---- epilogue: split-bf16 write (slot-0 lanes of each head) ----
    if (slot == 0) {
        alignas(8) __nv_bfloat16 h[4], lo[4];
        h[0] = __float2bfloat16(a0); lo[0] = __float2bfloat16(a0 - __bfloat162float(h[0]));
        h[1] = __float2bfloat16(a1); lo[1] = __float2bfloat16(a1 - __bfloat162float(h[1]));
        h[2] = __float2bfloat16(a2); lo[2] = __float2bfloat16(a2 - __bfloat162float(h[2]));
        h[3] = __float2bfloat16(a3); lo[3] = __float2bfloat16(a3 - __bfloat162float(h[3]));
        const size_t base = (size_t)bq * KSPLIT + myhead * 32 + c4 * 4;
        *(uint2*)(outs + base)       = *(uint2*)h;
        *(uint2*)(outs + base + 256) = *(uint2*)lo;
    }
}

// ---------------------------------------------------------------------------
// Launch (4 launches total)
// ---------------------------------------------------------------------------
extern "C" void kernel_launch(void* const* d_in, const int* in_sizes, int n_in,
                              void* d_out, int out_size)
{
    const float* query = (const float*)d_in[0];
    const float* value = (const float*)d_in[1];
    const float* refp  = (const float*)d_in[2];
    const float* Wv    = (const float*)d_in[3];
    const float* bv    = (const float*)d_in[4];
    const float* Wo    = (const float*)d_in[5];
    const float* bo    = (const float*)d_in[6];
    const float* Wa    = (const float*)d_in[7];
    const float* ba    = (const float*)d_in[8];
    const float* Wout  = (const float*)d_in[9];
    const float* bout  = (const float*)d_in[10];
    float* out = (float*)d_out;

    float *pvraw, *poff, *paw;
    __nv_bfloat16 *pAv, *pAq, *pAat, *pBv, *pBo, *pBa, *pBout;
    cudaGetSymbolAddress((void**)&pvraw, g_vbuf);
    cudaGetSymbolAddress((void**)&poff,  g_off);
    cudaGetSymbolAddress((void**)&paw,   g_aw);
    cudaGetSymbolAddress((void**)&pAv,   g_Av);
    cudaGetSymbolAddress((void**)&pAq,   g_Aq);
    cudaGetSymbolAddress((void**)&pAat,  g_Aat);
    cudaGetSymbolAddress((void**)&pBv,   g_Bv);
    cudaGetSymbolAddress((void**)&pBo,   g_Bo);
    cudaGetSymbolAddress((void**)&pBa,   g_Ba);
    cudaGetSymbolAddress((void**)&pBout, g_Bout);
    float* pv = pvraw + VPAD;

    cudaFuncSetAttribute(gemm_fused3, cudaFuncAttributeMaxDynamicSharedMemorySize, GSMEM);
    cudaFuncSetAttribute(gemm_out,    cudaFuncAttributeMaxDynamicSharedMemorySize, GSMEM);

    conv_all<<<11776, 256>>>(value, query, Wv, Wo, Wa, Wout,
                             pAv, pAq, pBv, pBo, pBa, pBout);

    gemm_fused3<<<850, 256, GSMEM>>>(pAv, pAq, pBv, pBo, pBa,
                                     bv, bo, ba, pv, poff, paw);

    msda_sample<<<MROWS / 2, 256>>>(pv, poff, paw, refp, pAat);

    gemm_out<<<340, 256, GSMEM>>>(pAat, pBout, bout, out);
}

// round 15
// speedup vs baseline: 1.0096x; 1.0096x over previous
#include <cuda_runtime.h>
#include <cuda_bf16.h>
#include <cstdint>

// ---------------------------------------------------------------------------
// Problem constants
// ---------------------------------------------------------------------------
#define EMBED   256
#define NHEADS  8
#define BATCH   4
#define NQ      5440
#define NV      5440
#define MROWS   (BATCH * NQ)   // 21760 = 170 * 128
#define KSPLIT  512            // [hi(256) | lo(256)] bf16

// ---------------------------------------------------------------------------
// Scratch (device globals; no allocation allowed)
// ---------------------------------------------------------------------------
#define VPAD    (66 * EMBED)
__device__ float g_vbuf[(size_t)VPAD + (size_t)MROWS * EMBED + (size_t)VPAD];
__device__ float g_off[(size_t)MROWS * EMBED];
__device__ float g_aw [(size_t)MROWS * 128];

__device__ __nv_bfloat16 g_Av [(size_t)MROWS * KSPLIT];  // value  split
__device__ __nv_bfloat16 g_Aq [(size_t)MROWS * KSPLIT];  // query  split
__device__ __nv_bfloat16 g_Aat[(size_t)MROWS * KSPLIT];  // attn-out split (from msda)
__device__ __nv_bfloat16 g_Bv  [256 * KSPLIT];           // weights split (K-major)
__device__ __nv_bfloat16 g_Bo  [256 * KSPLIT];
__device__ __nv_bfloat16 g_Ba  [128 * KSPLIT];
__device__ __nv_bfloat16 g_Bout[256 * KSPLIT];

// ---------------------------------------------------------------------------
// PTX helpers (baseline compute_103-safe)
// ---------------------------------------------------------------------------
__device__ __forceinline__ uint32_t smem_u32(const void* p) {
    uint32_t a;
    asm("{ .reg .u64 t; cvta.to.shared.u64 t, %1; cvt.u32.u64 %0, t; }"
        : "=r"(a) : "l"(p));
    return a;
}
__device__ __forceinline__ void cp_async16(uint32_t dst, const void* src) {
    asm volatile("cp.async.cg.shared.global [%0], [%1], 16;"
                 :: "r"(dst), "l"(src) : "memory");
}
__device__ __forceinline__ void cp_commit() {
    asm volatile("cp.async.commit_group;" ::: "memory");
}
template <int N>
__device__ __forceinline__ void cp_wait() {
    asm volatile("cp.async.wait_group %0;" :: "n"(N) : "memory");
}
__device__ __forceinline__ void ldsm_x4(uint32_t& r0, uint32_t& r1,
                                        uint32_t& r2, uint32_t& r3, uint32_t a) {
    asm volatile("ldmatrix.sync.aligned.m8n8.x4.shared.b16 {%0,%1,%2,%3}, [%4];"
                 : "=r"(r0), "=r"(r1), "=r"(r2), "=r"(r3) : "r"(a));
}
__device__ __forceinline__ void mma16816(float* d, const uint32_t* a,
                                         uint32_t b0, uint32_t b1) {
    asm volatile(
        "mma.sync.aligned.m16n8k16.row.col.f32.bf16.bf16.f32 "
        "{%0,%1,%2,%3}, {%4,%5,%6,%7}, {%8,%9}, {%0,%1,%2,%3};"
        : "+f"(d[0]), "+f"(d[1]), "+f"(d[2]), "+f"(d[3])
        : "r"(a[0]), "r"(a[1]), "r"(a[2]), "r"(a[3]), "r"(b0), "r"(b1));
}

// ---------------------------------------------------------------------------
// Fused fp32 -> split-bf16 conversion (activations + all 4 weight matrices)
// ---------------------------------------------------------------------------
__device__ __forceinline__ void conv_act_body(
    const float* __restrict__ in, __nv_bfloat16* __restrict__ out, int i)
{
    int r = i >> 6, k4 = (i & 63) << 2;
    float4 x = *(const float4*)(in + (size_t)r * 256 + k4);
    alignas(8) __nv_bfloat16 h[4], l[4];
    h[0] = __float2bfloat16(x.x); l[0] = __float2bfloat16(x.x - __bfloat162float(h[0]));
    h[1] = __float2bfloat16(x.y); l[1] = __float2bfloat16(x.y - __bfloat162float(h[1]));
    h[2] = __float2bfloat16(x.z); l[2] = __float2bfloat16(x.z - __bfloat162float(h[2]));
    h[3] = __float2bfloat16(x.w); l[3] = __float2bfloat16(x.w - __bfloat162float(h[3]));
    *(uint2*)(out + (size_t)r * KSPLIT + k4)       = *(uint2*)h;
    *(uint2*)(out + (size_t)r * KSPLIT + 256 + k4) = *(uint2*)l;
}
__device__ __forceinline__ void conv_wt_body(
    const float* __restrict__ W, __nv_bfloat16* __restrict__ out, int N, int i)
{
    int n = i >> 8, k = i & 255;
    float x = W[(size_t)k * N + n];
    __nv_bfloat16 h = __float2bfloat16(x);
    out[(size_t)n * KSPLIT + k]       = h;
    out[(size_t)n * KSPLIT + 256 + k] = __float2bfloat16(x - __bfloat162float(h));
}

// grid segments: [0,5440) value, [5440,10880) query,
// [10880,11136) Wv, [11136,11392) Wo, [11392,11520) Wa, [11520,11776) Wout
__global__ __launch_bounds__(256) void conv_all(
    const float* __restrict__ value, const float* __restrict__ query,
    const float* __restrict__ Wv, const float* __restrict__ Wo,
    const float* __restrict__ Wa, const float* __restrict__ Wout,
    __nv_bfloat16* __restrict__ Av, __nv_bfloat16* __restrict__ Aq,
    __nv_bfloat16* __restrict__ Bv, __nv_bfloat16* __restrict__ Bo,
    __nv_bfloat16* __restrict__ Ba, __nv_bfloat16* __restrict__ Bout)
{
    const int id = blockIdx.x, tid = threadIdx.x;
    if (id < 5440) {
        conv_act_body(value, Av, id * 256 + tid);
    } else if (id < 10880) {
        conv_act_body(query, Aq, (id - 5440) * 256 + tid);
    } else if (id < 11136) {
        conv_wt_body(Wv, Bv, 256, (id - 10880) * 256 + tid);
    } else if (id < 11392) {
        conv_wt_body(Wo, Bo, 256, (id - 11136) * 256 + tid);
    } else if (id < 11520) {
        conv_wt_body(Wa, Ba, 128, (id - 11392) * 256 + tid);
    } else {
        conv_wt_body(Wout, Bout, 256, (id - 11520) * 256 + tid);
    }
}

// ---------------------------------------------------------------------------
// HMMA GEMM body v6: R11/R13 config (CTA 128x128, 8 warps @ 64x32, 3-stage
// cp.async ring) + FRAGMENT DOUBLE-BUFFERING. While the mmas of k-slice ks
// consume fragment buffer ks&1, the ldsm for ks+1 issues into the other
// buffer with no dependency on in-flight mmas — hiding LDSM result latency
// behind the 16-mma block and keeping each warp's issue stream continuous
// (the R12/R14 evidence says this kernel is per-warp dependency bound, not
// crossbar or stagger bound).
// ---------------------------------------------------------------------------
#define NCHUNK 12
#define STG    32768                 // A(16K) + B(16K) per stage
#define GSMEM  (3 * STG)             // 96 KB

__device__ __forceinline__ void gemm_body(
    const __nv_bfloat16* __restrict__ A, const __nv_bfloat16* __restrict__ B,
    const float* __restrict__ bias, float* __restrict__ C, int N,
    int r0, int c0, char* smem)
{
    const uint32_t sb = smem_u32(smem);
    const int tid = threadIdx.x, wid = tid >> 5, lane = tid & 31;
    const int warp_m = wid & 1, warp_n = wid >> 1;   // 2 x 4 warp grid

    const int cpRow = tid >> 1;          // 0..127
    const int cpU0  = (tid & 1) * 4;     // 0 or 4 (16B units)

    auto prefetch = [&](int c, int st) {
        const int p  = c >> 2, kc = c & 3;
        const int ka = ((p == 1) ? 256 : 0) + kc * 64;
        const int kb = ((p == 2) ? 256 : 0) + kc * 64;
        const __nv_bfloat16* ga = A + (size_t)(r0 + cpRow) * KSPLIT + ka + cpU0 * 8;
        const __nv_bfloat16* gb = B + (size_t)(c0 + cpRow) * KSPLIT + kb + cpU0 * 8;
        const uint32_t sa = sb + st * STG + cpRow * 128;
        const uint32_t sg = sa + 16384;
        const int swz = cpRow & 7;
#pragma unroll
        for (int i = 0; i < 4; i++) {
            const int u = cpU0 + i;
            cp_async16(sa + ((u ^ swz) << 4), ga + i * 8);
            cp_async16(sg + ((u ^ swz) << 4), gb + i * 8);
        }
        cp_commit();
    };

    const int r7   = lane & 7;
    const int arow = (lane & 7) | (((lane >> 3) & 1) << 3);
    const int ah   = (lane >> 4) & 1;
    const int brow = (lane & 7) | (((lane >> 4) & 1) << 3);
    const int bh   = (lane >> 3) & 1;

    float acc[4][4][4];
#pragma unroll
    for (int mi = 0; mi < 4; mi++)
#pragma unroll
        for (int ni = 0; ni < 4; ni++)
#pragma unroll
            for (int j = 0; j < 4; j++) acc[mi][ni][j] = 0.f;

    prefetch(0, 0);
    prefetch(1, 1);

    uint32_t af[2][4][4];        // double-buffered A fragments
    uint32_t bf[2][4][2];        // double-buffered B fragments

    for (int c = 0; c < NCHUNK; c++) {
        if (c + 1 < NCHUNK) cp_wait<1>(); else cp_wait<0>();
        __syncthreads();
        if (c + 2 < NCHUNK) prefetch(c + 2, (c + 2) % 3);

        const uint32_t Ast = sb + (c % 3) * STG;
        const uint32_t Bst = Ast + 16384;

        // fragment loader for k-slice ks into buffer bufi
        auto ldfrags = [&](int ks, int bufi) {
#pragma unroll
            for (int mi = 0; mi < 4; mi++) {
                const int row = warp_m * 64 + mi * 16 + arow;
                const uint32_t addr = Ast + row * 128 + (((ks * 2 + ah) ^ r7) << 4);
                ldsm_x4(af[bufi][mi][0], af[bufi][mi][1],
                        af[bufi][mi][2], af[bufi][mi][3], addr);
            }
#pragma unroll
            for (int nh = 0; nh < 2; nh++) {
                const int row = warp_n * 32 + nh * 16 + brow;
                const uint32_t addr = Bst + row * 128 + (((ks * 2 + bh) ^ r7) << 4);
                uint32_t t0, t1, t2, t3;
                ldsm_x4(t0, t1, t2, t3, addr);
                bf[bufi][nh * 2][0] = t0; bf[bufi][nh * 2][1] = t1;
                bf[bufi][nh * 2 + 1][0] = t2; bf[bufi][nh * 2 + 1][1] = t3;
            }
        };

        ldfrags(0, 0);
#pragma unroll
        for (int ks = 0; ks < 4; ks++) {
            const int cur = ks & 1;
            if (ks < 3) ldfrags(ks + 1, cur ^ 1);   // independent of mmas below
#pragma unroll
            for (int mi = 0; mi < 4; mi++)
#pragma unroll
                for (int ni = 0; ni < 4; ni++)
                    mma16816(acc[mi][ni], af[cur][mi], bf[cur][ni][0], bf[cur][ni][1]);
        }
    }

    // epilogue: bias + store
    const int g = lane >> 2, tig = lane & 3;
    float2 bb[4];
#pragma unroll
    for (int ni = 0; ni < 4; ni++)
        bb[ni] = *(const float2*)(bias + c0 + warp_n * 32 + ni * 8 + tig * 2);
#pragma unroll
    for (int mi = 0; mi < 4; mi++) {
        const int rowg = r0 + warp_m * 64 + mi * 16 + g;
        float* p0 = C + (size_t)rowg * N + c0 + warp_n * 32 + tig * 2;
        float* p1 = p0 + (size_t)8 * N;
#pragma unroll
        for (int ni = 0; ni < 4; ni++) {
            float2 o0 = { acc[mi][ni][0] + bb[ni].x, acc[mi][ni][1] + bb[ni].y };
            float2 o1 = { acc[mi][ni][2] + bb[ni].x, acc[mi][ni][3] + bb[ni].y };
            *(float2*)(p0 + ni * 8) = o0;
            *(float2*)(p1 + ni * 8) = o1;
        }
    }
}

// Fused: seg0 value-proj (340 CTAs), seg1 offsets (340), seg2 logits (170)
__global__ __launch_bounds__(256, 2) void gemm_fused3(
    const __nv_bfloat16* __restrict__ Av, const __nv_bfloat16* __restrict__ Aq,
    const __nv_bfloat16* __restrict__ Bv, const __nv_bfloat16* __restrict__ Bo,
    const __nv_bfloat16* __restrict__ Ba,
    const float* __restrict__ bv, const float* __restrict__ bo,
    const float* __restrict__ ba,
    float* __restrict__ Cv, float* __restrict__ Co, float* __restrict__ Ca)
{
    extern __shared__ char smem[];
    int id = blockIdx.x;
    if (id < 340) {
        gemm_body(Av, Bv, bv, Cv, 256, (id >> 1) * 128, (id & 1) * 128, smem);
    } else if (id < 680) {
        id -= 340;
        gemm_body(Aq, Bo, bo, Co, 256, (id >> 1) * 128, (id & 1) * 128, smem);
    } else {
        id -= 680;
        gemm_body(Aq, Ba, ba, Ca, 128, id * 128, 0, smem);
    }
}

__global__ __launch_bounds__(256, 2) void gemm_out(
    const __nv_bfloat16* __restrict__ A, const __nv_bfloat16* __restrict__ B,
    const float* __restrict__ bias, float* __restrict__ C)
{
    extern __shared__ char smem[];
    gemm_body(A, B, bias, C, 256, (blockIdx.x >> 1) * 128, (blockIdx.x & 1) * 128, smem);
}

// ---------------------------------------------------------------------------
// Deformable sampling v4 (unchanged from R13): one warp per (b, q, head-pair).
// ---------------------------------------------------------------------------
__global__ __launch_bounds__(256) void msda_sample(
    const float* __restrict__ v, const float* __restrict__ off,
    const float* __restrict__ aw, const float* __restrict__ ref,
    __nv_bfloat16* __restrict__ outs)   // (B*NQ, 512) = [hi|lo]
{
    const int wid  = threadIdx.x >> 5;            // 0..7
    const int lane = threadIdx.x & 31;
    const int bq   = blockIdx.x * 2 + (wid >> 2); // 2 queries per block
    const int hp   = wid & 3;                     // head pair 0..3
    const int b    = bq / NQ;
    const unsigned FULL = 0xffffffffu;

    const int head_sel = lane >> 4;               // 0 or 1
    const int j        = lane & 15;               // point index within head

    // ---- softmax over 16 logits, both heads at once (width-16 lanes) ----
    const float a = aw[((size_t)bq * NHEADS + hp * 2) * 16 + lane];
    float m = a;
#pragma unroll
    for (int o = 8; o; o >>= 1) m = fmaxf(m, __shfl_xor_sync(FULL, m, o));
    const float e = expf(a - m);
    float s = e;
#pragma unroll
    for (int o = 8; o; o >>= 1) s += __shfl_xor_sync(FULL, s, o);
    const float p = e / s;    // prob of this lane's point

    // ---- phase 1: every lane computes its point's base offset + weights ----
    const float* offp = off + (size_t)bq * EMBED + hp * 64;
    const float offv0 = offp[lane];          // head 2hp   : pts 0-15 (x,y)
    const float offv1 = offp[32 + lane];     // head 2hp+1 : pts 0-15 (x,y)
    const float oxA = __shfl_sync(FULL, offv0, 2 * j);
    const float oyA = __shfl_sync(FULL, offv0, 2 * j + 1);
    const float oxB = __shfl_sync(FULL, offv1, 2 * j);
    const float oyB = __shfl_sync(FULL, offv1, 2 * j + 1);
    const float ox = head_sel ? oxB : oxA;
    const float oy = head_sel ? oyB : oyA;

    const float refv = (lane < 8) ? ref[(size_t)bq * 8 + lane] : 0.f;
    const int   l  = (j >> 2) & 3;                // level of this point
    const float rx = __shfl_sync(FULL, refv, 2 * l);
    const float ry = __shfl_sync(FULL, refv, 2 * l + 1);

    const int   Wi  = 64 >> l;
    const float Wf  = (float)Wi;
    const int   cur = (16384 - (16384 >> (2 * l))) / 3;

    const float px = (rx + ox / Wf) * Wf - 0.5f;
    const float py = (ry + oy / Wf) * Wf - 0.5f;
    const float x0f = floorf(px), y0f = floorf(py);
    const float wx = px - x0f,    wy = py - y0f;
    const int x0 = (int)x0f, y0 = (int)y0f;

    const bool vx0 = (x0 >= 0)  & (x0 < Wi);
    const bool vx1 = (x0 >= -1) & (x0 < Wi - 1);
    const bool vy0 = (y0 >= 0)  & (y0 < Wi);
    const bool vy1 = (y0 >= -1) & (y0 < Wi - 1);
    const float u = 1.f - wx, t = 1.f - wy;

    float c00 = (vx0 && vy0) ? p * u  * t  : 0.f;
    float c10 = (vx1 && vy0) ? p * wx * t  : 0.f;
    float c01 = (vx0 && vy1) ? p * u  * wy : 0.f;
    float c11 = (vx1 && vy1) ? p * wx * wy : 0.f;

    int idx = cur + y0 * Wi + x0;
    idx = min(max(idx, -65), NV - 1);
    const int o00 = idx << 10;

    // ---- phase 2: 8 iterations; this lane gathers point (it*2 + slot) of
    //      head (2hp + head_sel), channel quad c4 ----
    const int slot = (lane >> 3) & 1;
    const int c4   = lane & 7;
    const int myhead = hp * 2 + head_sel;
    const char* vb = (const char*)(v + (size_t)b * NV * EMBED + myhead * 32 + c4 * 4);
    const int srcbase = head_sel * 16 + slot;     // shfl source lane base

    float a0 = 0.f, a1 = 0.f, a2 = 0.f, a3 = 0.f;
#pragma unroll
    for (int it = 0; it < 8; it++) {
        const int rowB = (64 >> (it >> 1)) << 10;   // level = it>>1 (uniform)
        const int src  = srcbase + it * 2;          // point j = it*2 + slot
        const int   io  = __shfl_sync(FULL, o00, src);
        const float w00 = __shfl_sync(FULL, c00, src);
        const float w10 = __shfl_sync(FULL, c10, src);
        const float w01 = __shfl_sync(FULL, c01, src);
        const float w11 = __shfl_sync(FULL, c11, src);
        const char* ad = vb + io;
        const float4 v00 = *(const float4*)(ad);
        const float4 v10 = *(const float4*)(ad + 1024);
        const float4 v01 = *(const float4*)(ad + rowB);
        const float4 v11 = *(const float4*)(ad + rowB + 1024);
        a0 = fmaf(w00, v00.x, a0); a1 = fmaf(w00, v00.y, a1);
        a2 = fmaf(w00, v00.z, a2); a3 = fmaf(w00, v00.w, a3);
        a0 = fmaf(w10, v10.x, a0); a1 = fmaf(w10, v10.y, a1);
        a2 = fmaf(w10, v10.z, a2); a3 = fmaf(w10, v10.w, a3);
        a0 = fmaf(w01, v01.x, a0); a1 = fmaf(w01, v01.y, a1);
        a2 = fmaf(w01, v01.z, a2); a3 = fmaf(w01, v01.w, a3);
        a0 = fmaf(w11, v11.x, a0); a1 = fmaf(w11, v11.y, a1);
        a2 = fmaf(w11, v11.z, a2); a3 = fmaf(w11, v11.w, a3);
    }
    // combine the two point slots of this head (lane bit 3)
    a0 += __shfl_xor_sync(FULL, a0, 8);  a1 += __shfl_xor_sync(FULL, a1, 8);
    a2 += __shfl_xor_sync(FULL, a2, 8);  a3 += __shfl_xor_sync(FULL, a3, 8);

    // ---- epilogue: split-bf16 write (slot-0 lanes of each head) ----
    if (slot == 0) {
        alignas(8) __nv_bfloat16 h[4], lo[4];
        h[0] = __float2bfloat16(a0); lo[0] = __float2bfloat16(a0 - __bfloat162float(h[0]));
        h[1] = __float2bfloat16(a1); lo[1] = __float2bfloat16(a1 - __bfloat162float(h[1]));
        h[2] = __float2bfloat16(a2); lo[2] = __float2bfloat16(a2 - __bfloat162float(h[2]));
        h[3] = __float2bfloat16(a3); lo[3] = __float2bfloat16(a3 - __bfloat162float(h[3]));
        const size_t base = (size_t)bq * KSPLIT + myhead * 32 + c4 * 4;
        *(uint2*)(outs + base)       = *(uint2*)h;
        *(uint2*)(outs + base + 256) = *(uint2*)lo;
    }
}

// ---------------------------------------------------------------------------
// Launch (4 launches total)
// ---------------------------------------------------------------------------
extern "C" void kernel_launch(void* const* d_in, const int* in_sizes, int n_in,
                              void* d_out, int out_size)
{
    const float* query = (const float*)d_in[0];
    const float* value = (const float*)d_in[1];
    const float* refp  = (const float*)d_in[2];
    const float* Wv    = (const float*)d_in[3];
    const float* bv    = (const float*)d_in[4];
    const float* Wo    = (const float*)d_in[5];
    const float* bo    = (const float*)d_in[6];
    const float* Wa    = (const float*)d_in[7];
    const float* ba    = (const float*)d_in[8];
    const float* Wout  = (const float*)d_in[9];
    const float* bout  = (const float*)d_in[10];
    float* out = (float*)d_out;

    float *pvraw, *poff, *paw;
    __nv_bfloat16 *pAv, *pAq, *pAat, *pBv, *pBo, *pBa, *pBout;
    cudaGetSymbolAddress((void**)&pvraw, g_vbuf);
    cudaGetSymbolAddress((void**)&poff,  g_off);
    cudaGetSymbolAddress((void**)&paw,   g_aw);
    cudaGetSymbolAddress((void**)&pAv,   g_Av);
    cudaGetSymbolAddress((void**)&pAq,   g_Aq);
    cudaGetSymbolAddress((void**)&pAat,  g_Aat);
    cudaGetSymbolAddress((void**)&pBv,   g_Bv);
    cudaGetSymbolAddress((void**)&pBo,   g_Bo);
    cudaGetSymbolAddress((void**)&pBa,   g_Ba);
    cudaGetSymbolAddress((void**)&pBout, g_Bout);
    float* pv = pvraw + VPAD;

    cudaFuncSetAttribute(gemm_fused3, cudaFuncAttributeMaxDynamicSharedMemorySize, GSMEM);
    cudaFuncSetAttribute(gemm_out,    cudaFuncAttributeMaxDynamicSharedMemorySize, GSMEM);

    conv_all<<<11776, 256>>>(value, query, Wv, Wo, Wa, Wout,
                             pAv, pAq, pBv, pBo, pBa, pBout);

    gemm_fused3<<<850, 256, GSMEM>>>(pAv, pAq, pBv, pBo, pBa,
                                     bv, bo, ba, pv, poff, paw);

    msda_sample<<<MROWS / 2, 256>>>(pv, poff, paw, refp, pAat);

    gemm_out<<<340, 256, GSMEM>>>(pAat, pBout, bout, out);
}

// round 16
// speedup vs baseline: 1.0722x; 1.0621x over previous
#include <cuda_runtime.h>
#include <cuda_bf16.h>
#include <cstdint>

// ---------------------------------------------------------------------------
// Problem constants
// ---------------------------------------------------------------------------
#define EMBED   256
#define NHEADS  8
#define BATCH   4
#define NQ      5440
#define NV      5440
#define MROWS   (BATCH * NQ)   // 21760 = 170 * 128
#define KSPLIT  512            // [hi(256) | lo(256)] bf16

// ---------------------------------------------------------------------------
// Scratch (device globals; no allocation allowed)
// ---------------------------------------------------------------------------
#define VPAD    (66 * EMBED)
__device__ float g_vbuf[(size_t)VPAD + (size_t)MROWS * EMBED + (size_t)VPAD];
__device__ float g_off[(size_t)MROWS * EMBED];
__device__ float g_aw [(size_t)MROWS * 128];

__device__ __nv_bfloat16 g_Av [(size_t)MROWS * KSPLIT];  // value split (bf16)
__device__ __nv_bfloat16 g_Aat[(size_t)MROWS * KSPLIT];  // attn-out split (from msda)
__device__ __nv_bfloat16 g_Bv  [256 * KSPLIT];           // value-proj W split
__device__ __nv_bfloat16 g_Bout[256 * KSPLIT];           // out-proj W split

__device__ float g_Aq32[(size_t)MROWS * 256];            // query, tf32-rounded
__device__ float g_Bo32[256 * 256];                      // offsets W, K-major tf32
__device__ float g_Ba32[128 * 256];                      // logits  W, K-major tf32

// ---------------------------------------------------------------------------
// PTX helpers (baseline compute_103-safe)
// ---------------------------------------------------------------------------
__device__ __forceinline__ uint32_t smem_u32(const void* p) {
    uint32_t a;
    asm("{ .reg .u64 t; cvta.to.shared.u64 t, %1; cvt.u32.u64 %0, t; }"
        : "=r"(a) : "l"(p));
    return a;
}
__device__ __forceinline__ void cp_async16(uint32_t dst, const void* src) {
    asm volatile("cp.async.cg.shared.global [%0], [%1], 16;"
                 :: "r"(dst), "l"(src) : "memory");
}
__device__ __forceinline__ void cp_commit() {
    asm volatile("cp.async.commit_group;" ::: "memory");
}
template <int N>
__device__ __forceinline__ void cp_wait() {
    asm volatile("cp.async.wait_group %0;" :: "n"(N) : "memory");
}
__device__ __forceinline__ void ldsm_x4(uint32_t& r0, uint32_t& r1,
                                        uint32_t& r2, uint32_t& r3, uint32_t a) {
    asm volatile("ldmatrix.sync.aligned.m8n8.x4.shared.b16 {%0,%1,%2,%3}, [%4];"
                 : "=r"(r0), "=r"(r1), "=r"(r2), "=r"(r3) : "r"(a));
}
__device__ __forceinline__ void mma16816(float* d, const uint32_t* a,
                                         uint32_t b0, uint32_t b1) {
    asm volatile(
        "mma.sync.aligned.m16n8k16.row.col.f32.bf16.bf16.f32 "
        "{%0,%1,%2,%3}, {%4,%5,%6,%7}, {%8,%9}, {%0,%1,%2,%3};"
        : "+f"(d[0]), "+f"(d[1]), "+f"(d[2]), "+f"(d[3])
        : "r"(a[0]), "r"(a[1]), "r"(a[2]), "r"(a[3]), "r"(b0), "r"(b1));
}
__device__ __forceinline__ void mma1688t(float* d, const uint32_t* a,
                                         uint32_t b0, uint32_t b1) {
    asm volatile(
        "mma.sync.aligned.m16n8k8.row.col.f32.tf32.tf32.f32 "
        "{%0,%1,%2,%3}, {%4,%5,%6,%7}, {%8,%9}, {%0,%1,%2,%3};"
        : "+f"(d[0]), "+f"(d[1]), "+f"(d[2]), "+f"(d[3])
        : "r"(a[0]), "r"(a[1]), "r"(a[2]), "r"(a[3]), "r"(b0), "r"(b1));
}
__device__ __forceinline__ float tf32r(float x) {
    uint32_t u;
    asm("cvt.rna.tf32.f32 %0, %1;" : "=r"(u) : "f"(x));
    return __uint_as_float(u);
}

// ---------------------------------------------------------------------------
// Fused conversions: value->bf16 split, query->tf32, W's per consumer
// ---------------------------------------------------------------------------
__device__ __forceinline__ void conv_act_body(
    const float* __restrict__ in, __nv_bfloat16* __restrict__ out, int i)
{
    int r = i >> 6, k4 = (i & 63) << 2;
    float4 x = *(const float4*)(in + (size_t)r * 256 + k4);
    alignas(8) __nv_bfloat16 h[4], l[4];
    h[0] = __float2bfloat16(x.x); l[0] = __float2bfloat16(x.x - __bfloat162float(h[0]));
    h[1] = __float2bfloat16(x.y); l[1] = __float2bfloat16(x.y - __bfloat162float(h[1]));
    h[2] = __float2bfloat16(x.z); l[2] = __float2bfloat16(x.z - __bfloat162float(h[2]));
    h[3] = __float2bfloat16(x.w); l[3] = __float2bfloat16(x.w - __bfloat162float(h[3]));
    *(uint2*)(out + (size_t)r * KSPLIT + k4)       = *(uint2*)h;
    *(uint2*)(out + (size_t)r * KSPLIT + 256 + k4) = *(uint2*)l;
}
__device__ __forceinline__ void conv_wt_body(
    const float* __restrict__ W, __nv_bfloat16* __restrict__ out, int N, int i)
{
    int n = i >> 8, k = i & 255;
    float x = W[(size_t)k * N + n];
    __nv_bfloat16 h = __float2bfloat16(x);
    out[(size_t)n * KSPLIT + k]       = h;
    out[(size_t)n * KSPLIT + 256 + k] = __float2bfloat16(x - __bfloat162float(h));
}

// grid segments: [0,5440) value->bf16, [5440,10880) query->tf32,
// [10880,11136) Wv bf16, [11136,11392) Wo tf32, [11392,11520) Wa tf32,
// [11520,11776) Wout bf16
__global__ __launch_bounds__(256) void conv_all(
    const float* __restrict__ value, const float* __restrict__ query,
    const float* __restrict__ Wv, const float* __restrict__ Wo,
    const float* __restrict__ Wa, const float* __restrict__ Wout,
    __nv_bfloat16* __restrict__ Av, float* __restrict__ Aq32,
    __nv_bfloat16* __restrict__ Bv, float* __restrict__ Bo32,
    float* __restrict__ Ba32, __nv_bfloat16* __restrict__ Bout)
{
    const int id = blockIdx.x, tid = threadIdx.x;
    if (id < 5440) {
        conv_act_body(value, Av, id * 256 + tid);
    } else if (id < 10880) {
        const int i = (id - 5440) * 256 + tid;
        const int r = i >> 6, k4 = (i & 63) << 2;
        float4 x = *(const float4*)(query + (size_t)r * 256 + k4);
        x.x = tf32r(x.x); x.y = tf32r(x.y); x.z = tf32r(x.z); x.w = tf32r(x.w);
        *(float4*)(Aq32 + (size_t)r * 256 + k4) = x;
    } else if (id < 11136) {
        conv_wt_body(Wv, Bv, 256, (id - 10880) * 256 + tid);
    } else if (id < 11392) {
        const int i = (id - 11136) * 256 + tid;
        const int n = i >> 8, k = i & 255;
        Bo32[n * 256 + k] = tf32r(Wo[(size_t)k * 256 + n]);
    } else if (id < 11520) {
        const int i = (id - 11392) * 256 + tid;
        const int n = i >> 8, k = i & 255;
        Ba32[n * 256 + k] = tf32r(Wa[(size_t)k * 128 + n]);
    } else {
        conv_wt_body(Wout, Bout, 256, (id - 11520) * 256 + tid);
    }
}

// ---------------------------------------------------------------------------
// bf16 HMMA GEMM body (R15 best): CTA 128x128, 8 warps @ 64x32, 12 chunks,
// 3-stage cp.async ring, fragment double-buffering.
// ---------------------------------------------------------------------------
#define NCHUNK 12
#define STG    32768                 // 32 KB per stage (both dtypes)
#define GSMEM  (3 * STG)             // 96 KB

__device__ __forceinline__ void gemm_body(
    const __nv_bfloat16* __restrict__ A, const __nv_bfloat16* __restrict__ B,
    const float* __restrict__ bias, float* __restrict__ C, int N,
    int r0, int c0, char* smem)
{
    const uint32_t sb = smem_u32(smem);
    const int tid = threadIdx.x, wid = tid >> 5, lane = tid & 31;
    const int warp_m = wid & 1, warp_n = wid >> 1;

    const int cpRow = tid >> 1;
    const int cpU0  = (tid & 1) * 4;

    auto prefetch = [&](int c, int st) {
        const int p  = c >> 2, kc = c & 3;
        const int ka = ((p == 1) ? 256 : 0) + kc * 64;
        const int kb = ((p == 2) ? 256 : 0) + kc * 64;
        const __nv_bfloat16* ga = A + (size_t)(r0 + cpRow) * KSPLIT + ka + cpU0 * 8;
        const __nv_bfloat16* gb = B + (size_t)(c0 + cpRow) * KSPLIT + kb + cpU0 * 8;
        const uint32_t sa = sb + st * STG + cpRow * 128;
        const uint32_t sg = sa + 16384;
        const int swz = cpRow & 7;
#pragma unroll
        for (int i = 0; i < 4; i++) {
            const int u = cpU0 + i;
            cp_async16(sa + ((u ^ swz) << 4), ga + i * 8);
            cp_async16(sg + ((u ^ swz) << 4), gb + i * 8);
        }
        cp_commit();
    };

    const int r7   = lane & 7;
    const int arow = (lane & 7) | (((lane >> 3) & 1) << 3);
    const int ah   = (lane >> 4) & 1;
    const int brow = (lane & 7) | (((lane >> 4) & 1) << 3);
    const int bh   = (lane >> 3) & 1;

    float acc[4][4][4];
#pragma unroll
    for (int mi = 0; mi < 4; mi++)
#pragma unroll
        for (int ni = 0; ni < 4; ni++)
#pragma unroll
            for (int j = 0; j < 4; j++) acc[mi][ni][j] = 0.f;

    prefetch(0, 0);
    prefetch(1, 1);

    uint32_t af[2][4][4];
    uint32_t bf[2][4][2];

    for (int c = 0; c < NCHUNK; c++) {
        if (c + 1 < NCHUNK) cp_wait<1>(); else cp_wait<0>();
        __syncthreads();
        if (c + 2 < NCHUNK) prefetch(c + 2, (c + 2) % 3);

        const uint32_t Ast = sb + (c % 3) * STG;
        const uint32_t Bst = Ast + 16384;

        auto ldfrags = [&](int ks, int bufi) {
#pragma unroll
            for (int mi = 0; mi < 4; mi++) {
                const int row = warp_m * 64 + mi * 16 + arow;
                const uint32_t addr = Ast + row * 128 + (((ks * 2 + ah) ^ r7) << 4);
                ldsm_x4(af[bufi][mi][0], af[bufi][mi][1],
                        af[bufi][mi][2], af[bufi][mi][3], addr);
            }
#pragma unroll
            for (int nh = 0; nh < 2; nh++) {
                const int row = warp_n * 32 + nh * 16 + brow;
                const uint32_t addr = Bst + row * 128 + (((ks * 2 + bh) ^ r7) << 4);
                uint32_t t0, t1, t2, t3;
                ldsm_x4(t0, t1, t2, t3, addr);
                bf[bufi][nh * 2][0] = t0; bf[bufi][nh * 2][1] = t1;
                bf[bufi][nh * 2 + 1][0] = t2; bf[bufi][nh * 2 + 1][1] = t3;
            }
        };

        ldfrags(0, 0);
#pragma unroll
        for (int ks = 0; ks < 4; ks++) {
            const int cur = ks & 1;
            if (ks < 3) ldfrags(ks + 1, cur ^ 1);
#pragma unroll
            for (int mi = 0; mi < 4; mi++)
#pragma unroll
                for (int ni = 0; ni < 4; ni++)
                    mma16816(acc[mi][ni], af[cur][mi], bf[cur][ni][0], bf[cur][ni][1]);
        }
    }

    const int g = lane >> 2, tig = lane & 3;
    float2 bb[4];
#pragma unroll
    for (int ni = 0; ni < 4; ni++)
        bb[ni] = *(const float2*)(bias + c0 + warp_n * 32 + ni * 8 + tig * 2);
#pragma unroll
    for (int mi = 0; mi < 4; mi++) {
        const int rowg = r0 + warp_m * 64 + mi * 16 + g;
        float* p0 = C + (size_t)rowg * N + c0 + warp_n * 32 + tig * 2;
        float* p1 = p0 + (size_t)8 * N;
#pragma unroll
        for (int ni = 0; ni < 4; ni++) {
            float2 o0 = { acc[mi][ni][0] + bb[ni].x, acc[mi][ni][1] + bb[ni].y };
            float2 o1 = { acc[mi][ni][2] + bb[ni].x, acc[mi][ni][3] + bb[ni].y };
            *(float2*)(p0 + ni * 8) = o0;
            *(float2*)(p1 + ni * 8) = o1;
        }
    }
}

// ---------------------------------------------------------------------------
// tf32 GEMM body: C[M,N] = rna(A32)[M,256] @ rna(B32)[N,256]^T + bias.
// Single pass, 8 chunks of K=32 (fp32 tiles, 16B-granule XOR swizzle,
// conflict-free per-lane LDS.32 fragment loads), mma.m16n8k8.tf32.
// 512 mma/warp-tile vs 768 for the 3-term bf16 split on an
// instruction-rate-bound tensor pipe.
// ---------------------------------------------------------------------------
#define NCHUNK_T 8

__device__ __forceinline__ void gemm_body_tf32(
    const float* __restrict__ A, const float* __restrict__ B,
    const float* __restrict__ bias, float* __restrict__ C, int N,
    int r0, int c0, char* smem)
{
    const uint32_t sb = smem_u32(smem);
    const int tid = threadIdx.x, wid = tid >> 5, lane = tid & 31;
    const int warp_m = wid & 1, warp_n = wid >> 1;

    const int cpRow = tid >> 1;
    const int cpU0  = (tid & 1) * 4;

    auto prefetch = [&](int c, int st) {
        const float* ga = A + (size_t)(r0 + cpRow) * 256 + c * 32;
        const float* gb = B + (size_t)(c0 + cpRow) * 256 + c * 32;
        const uint32_t sa = sb + st * STG + cpRow * 128;
        const uint32_t sg = sa + 16384;
        const int swz = cpRow & 7;
#pragma unroll
        for (int i = 0; i < 4; i++) {
            const int u = cpU0 + i;
            cp_async16(sa + ((u ^ swz) << 4), ga + u * 4);
            cp_async16(sg + ((u ^ swz) << 4), gb + u * 4);
        }
        cp_commit();
    };

    const int lq = lane >> 2;      // fragment row group 0..7
    const int lr = lane & 3;       // fragment k index 0..3

    float acc[4][4][4];
#pragma unroll
    for (int mi = 0; mi < 4; mi++)
#pragma unroll
        for (int ni = 0; ni < 4; ni++)
#pragma unroll
            for (int j = 0; j < 4; j++) acc[mi][ni][j] = 0.f;

    prefetch(0, 0);
    prefetch(1, 1);

    for (int c = 0; c < NCHUNK_T; c++) {
        if (c + 1 < NCHUNK_T) cp_wait<1>(); else cp_wait<0>();
        __syncthreads();
        if (c + 2 < NCHUNK_T) prefetch(c + 2, (c + 2) % 3);

        const char* As = smem + (c % 3) * STG;
        const char* Bs = As + 16384;

#pragma unroll
        for (int ks = 0; ks < 4; ks++) {
            uint32_t af[4][4];
#pragma unroll
            for (int mi = 0; mi < 4; mi++) {
                const int R = warp_m * 64 + mi * 16 + lq;
                const char* pa = As + R * 128 +
                                 ((((ks * 2) ^ (R & 7)) << 4) + lr * 4);
                const char* pa2 = As + R * 128 +
                                  ((((ks * 2 + 1) ^ (R & 7)) << 4) + lr * 4);
                af[mi][0] = *(const uint32_t*)pa;
                af[mi][1] = *(const uint32_t*)(pa + 1024);   // row +8
                af[mi][2] = *(const uint32_t*)pa2;
                af[mi][3] = *(const uint32_t*)(pa2 + 1024);
            }
            uint32_t bfr[4][2];
#pragma unroll
            for (int nj = 0; nj < 4; nj++) {
                const int n = warp_n * 32 + nj * 8 + lq;
                const char* pb = Bs + n * 128 +
                                 ((((ks * 2) ^ (n & 7)) << 4) + lr * 4);
                const char* pb2 = Bs + n * 128 +
                                  ((((ks * 2 + 1) ^ (n & 7)) << 4) + lr * 4);
                bfr[nj][0] = *(const uint32_t*)pb;
                bfr[nj][1] = *(const uint32_t*)pb2;
            }
#pragma unroll
            for (int mi = 0; mi < 4; mi++)
#pragma unroll
                for (int nj = 0; nj < 4; nj++)
                    mma1688t(acc[mi][nj], af[mi], bfr[nj][0], bfr[nj][1]);
        }
    }

    const int g = lane >> 2, tig = lane & 3;
    float2 bb[4];
#pragma unroll
    for (int ni = 0; ni < 4; ni++)
        bb[ni] = *(const float2*)(bias + c0 + warp_n * 32 + ni * 8 + tig * 2);
#pragma unroll
    for (int mi = 0; mi < 4; mi++) {
        const int rowg = r0 + warp_m * 64 + mi * 16 + g;
        float* p0 = C + (size_t)rowg * N + c0 + warp_n * 32 + tig * 2;
        float* p1 = p0 + (size_t)8 * N;
#pragma unroll
        for (int ni = 0; ni < 4; ni++) {
            float2 o0 = { acc[mi][ni][0] + bb[ni].x, acc[mi][ni][1] + bb[ni].y };
            float2 o1 = { acc[mi][ni][2] + bb[ni].x, acc[mi][ni][3] + bb[ni].y };
            *(float2*)(p0 + ni * 8) = o0;
            *(float2*)(p1 + ni * 8) = o1;
        }
    }
}

// Fused: seg0 value-proj bf16 (340), seg1 offsets tf32 (340), seg2 logits tf32 (170)
__global__ __launch_bounds__(256, 2) void gemm_fused3(
    const __nv_bfloat16* __restrict__ Av, const float* __restrict__ Aq32,
    const __nv_bfloat16* __restrict__ Bv, const float* __restrict__ Bo32,
    const float* __restrict__ Ba32,
    const float* __restrict__ bv, const float* __restrict__ bo,
    const float* __restrict__ ba,
    float* __restrict__ Cv, float* __restrict__ Co, float* __restrict__ Ca)
{
    extern __shared__ char smem[];
    int id = blockIdx.x;
    if (id < 340) {
        gemm_body(Av, Bv, bv, Cv, 256, (id >> 1) * 128, (id & 1) * 128, smem);
    } else if (id < 680) {
        id -= 340;
        gemm_body_tf32(Aq32, Bo32, bo, Co, 256, (id >> 1) * 128, (id & 1) * 128, smem);
    } else {
        id -= 680;
        gemm_body_tf32(Aq32, Ba32, ba, Ca, 128, id * 128, 0, smem);
    }
}

__global__ __launch_bounds__(256, 2) void gemm_out(
    const __nv_bfloat16* __restrict__ A, const __nv_bfloat16* __restrict__ B,
    const float* __restrict__ bias, float* __restrict__ C)
{
    extern __shared__ char smem[];
    gemm_body(A, B, bias, C, 256, (blockIdx.x >> 1) * 128, (blockIdx.x & 1) * 128, smem);
}

// ---------------------------------------------------------------------------
// Deformable sampling v4 (unchanged from R13): one warp per (b, q, head-pair).
// ---------------------------------------------------------------------------
__global__ __launch_bounds__(256) void msda_sample(
    const float* __restrict__ v, const float* __restrict__ off,
    const float* __restrict__ aw, const float* __restrict__ ref,
    __nv_bfloat16* __restrict__ outs)   // (B*NQ, 512) = [hi|lo]
{
    const int wid  = threadIdx.x >> 5;
    const int lane = threadIdx.x & 31;
    const int bq   = blockIdx.x * 2 + (wid >> 2);
    const int hp   = wid & 3;
    const int b    = bq / NQ;
    const unsigned FULL = 0xffffffffu;

    const int head_sel = lane >> 4;
    const int j        = lane & 15;

    const float a = aw[((size_t)bq * NHEADS + hp * 2) * 16 + lane];
    float m = a;
#pragma unroll
    for (int o = 8; o; o >>= 1) m = fmaxf(m, __shfl_xor_sync(FULL, m, o));
    const float e = expf(a - m);
    float s = e;
#pragma unroll
    for (int o = 8; o; o >>= 1) s += __shfl_xor_sync(FULL, s, o);
    const float p = e / s;

    const float* offp = off + (size_t)bq * EMBED + hp * 64;
    const float offv0 = offp[lane];
    const float offv1 = offp[32 + lane];
    const float oxA = __shfl_sync(FULL, offv0, 2 * j);
    const float oyA = __shfl_sync(FULL, offv0, 2 * j + 1);
    const float oxB = __shfl_sync(FULL, offv1, 2 * j);
    const float oyB = __shfl_sync(FULL, offv1, 2 * j + 1);
    const float ox = head_sel ? oxB : oxA;
    const float oy = head_sel ? oyB : oyA;

    const float refv = (lane < 8) ? ref[(size_t)bq * 8 + lane] : 0.f;
    const int   l  = (j >> 2) & 3;
    const float rx = __shfl_sync(FULL, refv, 2 * l);
    const float ry = __shfl_sync(FULL, refv, 2 * l + 1);

    const int   Wi  = 64 >> l;
    const float Wf  = (float)Wi;
    const int   cur = (16384 - (16384 >> (2 * l))) / 3;

    const float px = (rx + ox / Wf) * Wf - 0.5f;
    const float py = (ry + oy / Wf) * Wf - 0.5f;
    const float x0f = floorf(px), y0f = floorf(py);
    const float wx = px - x0f,    wy = py - y0f;
    const int x0 = (int)x0f, y0 = (int)y0f;

    const bool vx0 = (x0 >= 0)  & (x0 < Wi);
    const bool vx1 = (x0 >= -1) & (x0 < Wi - 1);
    const bool vy0 = (y0 >= 0)  & (y0 < Wi);
    const bool vy1 = (y0 >= -1) & (y0 < Wi - 1);
    const float u = 1.f - wx, t = 1.f - wy;

    float c00 = (vx0 && vy0) ? p * u  * t  : 0.f;
    float c10 = (vx1 && vy0) ? p * wx * t  : 0.f;
    float c01 = (vx0 && vy1) ? p * u  * wy : 0.f;
    float c11 = (vx1 && vy1) ? p * wx * wy : 0.f;

    int idx = cur + y0 * Wi + x0;
    idx = min(max(idx, -65), NV - 1);
    const int o00 = idx << 10;

    const int slot = (lane >> 3) & 1;
    const int c4   = lane & 7;
    const int myhead = hp * 2 + head_sel;
    const char* vb = (const char*)(v + (size_t)b * NV * EMBED + myhead * 32 + c4 * 4);
    const int srcbase = head_sel * 16 + slot;

    float a0 = 0.f, a1 = 0.f, a2 = 0.f, a3 = 0.f;
#pragma unroll
    for (int it = 0; it < 8; it++) {
        const int rowB = (64 >> (it >> 1)) << 10;
        const int src  = srcbase + it * 2;
        const int   io  = __shfl_sync(FULL, o00, src);
        const float w00 = __shfl_sync(FULL, c00, src);
        const float w10 = __shfl_sync(FULL, c10, src);
        const float w01 = __shfl_sync(FULL, c01, src);
        const float w11 = __shfl_sync(FULL, c11, src);
        const char* ad = vb + io;
        const float4 v00 = *(const float4*)(ad);
        const float4 v10 = *(const float4*)(ad + 1024);
        const float4 v01 = *(const float4*)(ad + rowB);
        const float4 v11 = *(const float4*)(ad + rowB + 1024);
        a0 = fmaf(w00, v00.x, a0); a1 = fmaf(w00, v00.y, a1);
        a2 = fmaf(w00, v00.z, a2); a3 = fmaf(w00, v00.w, a3);
        a0 = fmaf(w10, v10.x, a0); a1 = fmaf(w10, v10.y, a1);
        a2 = fmaf(w10, v10.z, a2); a3 = fmaf(w10, v10.w, a3);
        a0 = fmaf(w01, v01.x, a0); a1 = fmaf(w01, v01.y, a1);
        a2 = fmaf(w01, v01.z, a2); a3 = fmaf(w01, v01.w, a3);
        a0 = fmaf(w11, v11.x, a0); a1 = fmaf(w11, v11.y, a1);
        a2 = fmaf(w11, v11.z, a2); a3 = fmaf(w11, v11.w, a3);
    }
    a0 += __shfl_xor_sync(FULL, a0, 8);  a1 += __shfl_xor_sync(FULL, a1, 8);
    a2 += __shfl_xor_sync(FULL, a2, 8);  a3 += __shfl_xor_sync(FULL, a3, 8);

    if (slot == 0) {
        alignas(8) __nv_bfloat16 h[4], lo[4];
        h[0] = __float2bfloat16(a0); lo[0] = __float2bfloat16(a0 - __bfloat162float(h[0]));
        h[1] = __float2bfloat16(a1); lo[1] = __float2bfloat16(a1 - __bfloat162float(h[1]));
        h[2] = __float2bfloat16(a2); lo[2] = __float2bfloat16(a2 - __bfloat162float(h[2]));
        h[3] = __float2bfloat16(a3); lo[3] = __float2bfloat16(a3 - __bfloat162float(h[3]));
        const size_t base = (size_t)bq * KSPLIT + myhead * 32 + c4 * 4;
        *(uint2*)(outs + base)       = *(uint2*)h;
        *(uint2*)(outs + base + 256) = *(uint2*)lo;
    }
}

// ---------------------------------------------------------------------------
// Launch (4 launches total)
// ---------------------------------------------------------------------------
extern "C" void kernel_launch(void* const* d_in, const int* in_sizes, int n_in,
                              void* d_out, int out_size)
{
    const float* query = (const float*)d_in[0];
    const float* value = (const float*)d_in[1];
    const float* refp  = (const float*)d_in[2];
    const float* Wv    = (const float*)d_in[3];
    const float* bv    = (const float*)d_in[4];
    const float* Wo    = (const float*)d_in[5];
    const float* bo    = (const float*)d_in[6];
    const float* Wa    = (const float*)d_in[7];
    const float* ba    = (const float*)d_in[8];
    const float* Wout  = (const float*)d_in[9];
    const float* bout  = (const float*)d_in[10];
    float* out = (float*)d_out;

    float *pvraw, *poff, *paw, *pAq32, *pBo32, *pBa32;
    __nv_bfloat16 *pAv, *pAat, *pBv, *pBout;
    cudaGetSymbolAddress((void**)&pvraw, g_vbuf);
    cudaGetSymbolAddress((void**)&poff,  g_off);
    cudaGetSymbolAddress((void**)&paw,   g_aw);
    cudaGetSymbolAddress((void**)&pAv,   g_Av);
    cudaGetSymbolAddress((void**)&pAat,  g_Aat);
    cudaGetSymbolAddress((void**)&pBv,   g_Bv);
    cudaGetSymbolAddress((void**)&pBout, g_Bout);
    cudaGetSymbolAddress((void**)&pAq32, g_Aq32);
    cudaGetSymbolAddress((void**)&pBo32, g_Bo32);
    cudaGetSymbolAddress((void**)&pBa32, g_Ba32);
    float* pv = pvraw + VPAD;

    cudaFuncSetAttribute(gemm_fused3, cudaFuncAttributeMaxDynamicSharedMemorySize, GSMEM);
    cudaFuncSetAttribute(gemm_out,    cudaFuncAttributeMaxDynamicSharedMemorySize, GSMEM);

    conv_all<<<11776, 256>>>(value, query, Wv, Wo, Wa, Wout,
                             pAv, pAq32, pBv, pBo32, pBa32, pBout);

    gemm_fused3<<<850, 256, GSMEM>>>(pAv, pAq32, pBv, pBo32, pBa32,
                                     bv, bo, ba, pv, poff, paw);

    msda_sample<<<MROWS / 2, 256>>>(pv, poff, paw, refp, pAat);

    gemm_out<<<340, 256, GSMEM>>>(pAat, pBout, bout, out);
}

// round 17
// speedup vs baseline: 1.1854x; 1.1056x over previous
#include <cuda_runtime.h>
#include <cuda_bf16.h>
#include <cstdint>

// ---------------------------------------------------------------------------
// Problem constants
// ---------------------------------------------------------------------------
#define EMBED   256
#define NHEADS  8
#define BATCH   4
#define NQ      5440
#define NV      5440
#define MROWS   (BATCH * NQ)   // 21760 = 170 * 128

// ---------------------------------------------------------------------------
// Scratch (device globals; no allocation allowed)
// ---------------------------------------------------------------------------
#define VPAD    (66 * EMBED)
__device__ float g_vbuf[(size_t)VPAD + (size_t)MROWS * EMBED + (size_t)VPAD];
__device__ float g_off[(size_t)MROWS * EMBED];
__device__ float g_aw [(size_t)MROWS * 128];

__device__ float g_Av32[(size_t)MROWS * 256];   // value, tf32-rounded
__device__ float g_Aq32[(size_t)MROWS * 256];   // query, tf32-rounded
__device__ float g_At32[(size_t)MROWS * 256];   // attn output, tf32 (from msda)
__device__ float g_Bv32 [256 * 256];            // value-proj W, K-major tf32
__device__ float g_Bo32 [256 * 256];            // offsets W,    K-major tf32
__device__ float g_Ba32 [128 * 256];            // logits  W,    K-major tf32
__device__ float g_Bout32[256 * 256];           // out-proj W,   K-major tf32

// ---------------------------------------------------------------------------
// PTX helpers (baseline compute_103-safe)
// ---------------------------------------------------------------------------
__device__ __forceinline__ uint32_t smem_u32(const void* p) {
    uint32_t a;
    asm("{ .reg .u64 t; cvta.to.shared.u64 t, %1; cvt.u32.u64 %0, t; }"
        : "=r"(a) : "l"(p));
    return a;
}
__device__ __forceinline__ void cp_async16(uint32_t dst, const void* src) {
    asm volatile("cp.async.cg.shared.global [%0], [%1], 16;"
                 :: "r"(dst), "l"(src) : "memory");
}
__device__ __forceinline__ void cp_commit() {
    asm volatile("cp.async.commit_group;" ::: "memory");
}
template <int N>
__device__ __forceinline__ void cp_wait() {
    asm volatile("cp.async.wait_group %0;" :: "n"(N) : "memory");
}
__device__ __forceinline__ void mma1688t(float* d, const uint32_t* a,
                                         uint32_t b0, uint32_t b1) {
    asm volatile(
        "mma.sync.aligned.m16n8k8.row.col.f32.tf32.tf32.f32 "
        "{%0,%1,%2,%3}, {%4,%5,%6,%7}, {%8,%9}, {%0,%1,%2,%3};"
        : "+f"(d[0]), "+f"(d[1]), "+f"(d[2]), "+f"(d[3])
        : "r"(a[0]), "r"(a[1]), "r"(a[2]), "r"(a[3]), "r"(b0), "r"(b1));
}
__device__ __forceinline__ float tf32r(float x) {
    uint32_t u;
    asm("cvt.rna.tf32.f32 %0, %1;" : "=r"(u) : "f"(x));
    return __uint_as_float(u);
}

// ---------------------------------------------------------------------------
// Conversions: activations & weights -> tf32-rounded fp32 (K-major for W)
// grid segments: [0,5440) value, [5440,10880) query,
// [10880,11136) Wv, [11136,11392) Wo, [11392,11520) Wa, [11520,11776) Wout
// ---------------------------------------------------------------------------
__global__ __launch_bounds__(256) void conv_all(
    const float* __restrict__ value, const float* __restrict__ query,
    const float* __restrict__ Wv, const float* __restrict__ Wo,
    const float* __restrict__ Wa, const float* __restrict__ Wout,
    float* __restrict__ Av32, float* __restrict__ Aq32,
    float* __restrict__ Bv32, float* __restrict__ Bo32,
    float* __restrict__ Ba32, float* __restrict__ Bout32)
{
    const int id = blockIdx.x, tid = threadIdx.x;
    if (id < 10880) {
        const bool isQ = (id >= 5440);
        const int i = (isQ ? id - 5440 : id) * 256 + tid;
        const int r = i >> 6, k4 = (i & 63) << 2;
        const float* src = isQ ? query : value;
        float* dst = isQ ? Aq32 : Av32;
        float4 x = *(const float4*)(src + (size_t)r * 256 + k4);
        x.x = tf32r(x.x); x.y = tf32r(x.y); x.z = tf32r(x.z); x.w = tf32r(x.w);
        *(float4*)(dst + (size_t)r * 256 + k4) = x;
    } else if (id < 11136) {
        const int i = (id - 10880) * 256 + tid;
        const int n = i >> 8, k = i & 255;
        Bv32[n * 256 + k] = tf32r(Wv[(size_t)k * 256 + n]);
    } else if (id < 11392) {
        const int i = (id - 11136) * 256 + tid;
        const int n = i >> 8, k = i & 255;
        Bo32[n * 256 + k] = tf32r(Wo[(size_t)k * 256 + n]);
    } else if (id < 11520) {
        const int i = (id - 11392) * 256 + tid;
        const int n = i >> 8, k = i & 255;
        Ba32[n * 256 + k] = tf32r(Wa[(size_t)k * 128 + n]);
    } else {
        const int i = (id - 11520) * 256 + tid;
        const int n = i >> 8, k = i & 255;
        Bout32[n * 256 + k] = tf32r(Wout[(size_t)k * 256 + n]);
    }
}

// ---------------------------------------------------------------------------
// tf32 GEMM body (validated in R16): C[M,N] = A32[M,256] @ B32[N,256]^T + bias.
// CTA 128x128, 8 warps @ 64x32, 8 chunks of K=32 (fp32 tiles, 16B-granule
// XOR swizzle, per-lane LDS.32 fragment loads), mma.m16n8k8.tf32, 3-stage
// cp.async ring. 512 mma/warp-tile.
// ---------------------------------------------------------------------------
#define NCHUNK_T 8
#define STG    32768                 // 32 KB per stage
#define GSMEM  (3 * STG)             // 96 KB

__device__ __forceinline__ void gemm_body_tf32(
    const float* __restrict__ A, const float* __restrict__ B,
    const float* __restrict__ bias, float* __restrict__ C, int N,
    int r0, int c0, char* smem)
{
    const uint32_t sb = smem_u32(smem);
    const int tid = threadIdx.x, wid = tid >> 5, lane = tid & 31;
    const int warp_m = wid & 1, warp_n = wid >> 1;

    const int cpRow = tid >> 1;
    const int cpU0  = (tid & 1) * 4;

    auto prefetch = [&](int c, int st) {
        const float* ga = A + (size_t)(r0 + cpRow) * 256 + c * 32;
        const float* gb = B + (size_t)(c0 + cpRow) * 256 + c * 32;
        const uint32_t sa = sb + st * STG + cpRow * 128;
        const uint32_t sg = sa + 16384;
        const int swz = cpRow & 7;
#pragma unroll
        for (int i = 0; i < 4; i++) {
            const int u = cpU0 + i;
            cp_async16(sa + ((u ^ swz) << 4), ga + u * 4);
            cp_async16(sg + ((u ^ swz) << 4), gb + u * 4);
        }
        cp_commit();
    };

    const int lq = lane >> 2;      // fragment row group 0..7
    const int lr = lane & 3;       // fragment k index 0..3

    float acc[4][4][4];
#pragma unroll
    for (int mi = 0; mi < 4; mi++)
#pragma unroll
        for (int ni = 0; ni < 4; ni++)
#pragma unroll
            for (int j = 0; j < 4; j++) acc[mi][ni][j] = 0.f;

    prefetch(0, 0);
    prefetch(1, 1);

    for (int c = 0; c < NCHUNK_T; c++) {
        if (c + 1 < NCHUNK_T) cp_wait<1>(); else cp_wait<0>();
        __syncthreads();
        if (c + 2 < NCHUNK_T) prefetch(c + 2, (c + 2) % 3);

        const char* As = smem + (c % 3) * STG;
        const char* Bs = As + 16384;

#pragma unroll
        for (int ks = 0; ks < 4; ks++) {
            uint32_t af[4][4];
#pragma unroll
            for (int mi = 0; mi < 4; mi++) {
                const int R = warp_m * 64 + mi * 16 + lq;
                const char* pa = As + R * 128 +
                                 ((((ks * 2) ^ (R & 7)) << 4) + lr * 4);
                const char* pa2 = As + R * 128 +
                                  ((((ks * 2 + 1) ^ (R & 7)) << 4) + lr * 4);
                af[mi][0] = *(const uint32_t*)pa;
                af[mi][1] = *(const uint32_t*)(pa + 1024);   // row +8
                af[mi][2] = *(const uint32_t*)pa2;
                af[mi][3] = *(const uint32_t*)(pa2 + 1024);
            }
            uint32_t bfr[4][2];
#pragma unroll
            for (int nj = 0; nj < 4; nj++) {
                const int n = warp_n * 32 + nj * 8 + lq;
                const char* pb = Bs + n * 128 +
                                 ((((ks * 2) ^ (n & 7)) << 4) + lr * 4);
                const char* pb2 = Bs + n * 128 +
                                  ((((ks * 2 + 1) ^ (n & 7)) << 4) + lr * 4);
                bfr[nj][0] = *(const uint32_t*)pb;
                bfr[nj][1] = *(const uint32_t*)pb2;
            }
#pragma unroll
            for (int mi = 0; mi < 4; mi++)
#pragma unroll
                for (int nj = 0; nj < 4; nj++)
                    mma1688t(acc[mi][nj], af[mi], bfr[nj][0], bfr[nj][1]);
        }
    }

    const int g = lane >> 2, tig = lane & 3;
    float2 bb[4];
#pragma unroll
    for (int ni = 0; ni < 4; ni++)
        bb[ni] = *(const float2*)(bias + c0 + warp_n * 32 + ni * 8 + tig * 2);
#pragma unroll
    for (int mi = 0; mi < 4; mi++) {
        const int rowg = r0 + warp_m * 64 + mi * 16 + g;
        float* p0 = C + (size_t)rowg * N + c0 + warp_n * 32 + tig * 2;
        float* p1 = p0 + (size_t)8 * N;
#pragma unroll
        for (int ni = 0; ni < 4; ni++) {
            float2 o0 = { acc[mi][ni][0] + bb[ni].x, acc[mi][ni][1] + bb[ni].y };
            float2 o1 = { acc[mi][ni][2] + bb[ni].x, acc[mi][ni][3] + bb[ni].y };
            *(float2*)(p0 + ni * 8) = o0;
            *(float2*)(p1 + ni * 8) = o1;
        }
    }
}

// Fused: seg0 value-proj (340 CTAs), seg1 offsets (340), seg2 logits (170)
__global__ __launch_bounds__(256, 2) void gemm_fused3(
    const float* __restrict__ Av32, const float* __restrict__ Aq32,
    const float* __restrict__ Bv32, const float* __restrict__ Bo32,
    const float* __restrict__ Ba32,
    const float* __restrict__ bv, const float* __restrict__ bo,
    const float* __restrict__ ba,
    float* __restrict__ Cv, float* __restrict__ Co, float* __restrict__ Ca)
{
    extern __shared__ char smem[];
    int id = blockIdx.x;
    if (id < 340) {
        gemm_body_tf32(Av32, Bv32, bv, Cv, 256, (id >> 1) * 128, (id & 1) * 128, smem);
    } else if (id < 680) {
        id -= 340;
        gemm_body_tf32(Aq32, Bo32, bo, Co, 256, (id >> 1) * 128, (id & 1) * 128, smem);
    } else {
        id -= 680;
        gemm_body_tf32(Aq32, Ba32, ba, Ca, 128, id * 128, 0, smem);
    }
}

__global__ __launch_bounds__(256, 2) void gemm_out(
    const float* __restrict__ A, const float* __restrict__ B,
    const float* __restrict__ bias, float* __restrict__ C)
{
    extern __shared__ char smem[];
    gemm_body_tf32(A, B, bias, C, 256, (blockIdx.x >> 1) * 128, (blockIdx.x & 1) * 128, smem);
}

// ---------------------------------------------------------------------------
// Deformable sampling v4 (R13 structure): one warp per (b, q, head-pair).
// Epilogue now writes tf32-rounded fp32 rows of g_At32 (out-proj is tf32).
// ---------------------------------------------------------------------------
__global__ __launch_bounds__(256) void msda_sample(
    const float* __restrict__ v, const float* __restrict__ off,
    const float* __restrict__ aw, const float* __restrict__ ref,
    float* __restrict__ outs)   // (B*NQ, 256) tf32-rounded
{
    const int wid  = threadIdx.x >> 5;
    const int lane = threadIdx.x & 31;
    const int bq   = blockIdx.x * 2 + (wid >> 2);
    const int hp   = wid & 3;
    const int b    = bq / NQ;
    const unsigned FULL = 0xffffffffu;

    const int head_sel = lane >> 4;
    const int j        = lane & 15;

    // ---- softmax over 16 logits, both heads at once ----
    const float a = aw[((size_t)bq * NHEADS + hp * 2) * 16 + lane];
    float m = a;
#pragma unroll
    for (int o = 8; o; o >>= 1) m = fmaxf(m, __shfl_xor_sync(FULL, m, o));
    const float e = expf(a - m);
    float s = e;
#pragma unroll
    for (int o = 8; o; o >>= 1) s += __shfl_xor_sync(FULL, s, o);
    const float p = e / s;

    // ---- phase 1: every lane computes its point's base offset + weights ----
    const float* offp = off + (size_t)bq * EMBED + hp * 64;
    const float offv0 = offp[lane];
    const float offv1 = offp[32 + lane];
    const float oxA = __shfl_sync(FULL, offv0, 2 * j);
    const float oyA = __shfl_sync(FULL, offv0, 2 * j + 1);
    const float oxB = __shfl_sync(FULL, offv1, 2 * j);
    const float oyB = __shfl_sync(FULL, offv1, 2 * j + 1);
    const float ox = head_sel ? oxB : oxA;
    const float oy = head_sel ? oyB : oyA;

    const float refv = (lane < 8) ? ref[(size_t)bq * 8 + lane] : 0.f;
    const int   l  = (j >> 2) & 3;
    const float rx = __shfl_sync(FULL, refv, 2 * l);
    const float ry = __shfl_sync(FULL, refv, 2 * l + 1);

    const int   Wi  = 64 >> l;
    const float Wf  = (float)Wi;
    const int   cur = (16384 - (16384 >> (2 * l))) / 3;

    const float px = (rx + ox / Wf) * Wf - 0.5f;
    const float py = (ry + oy / Wf) * Wf - 0.5f;
    const float x0f = floorf(px), y0f = floorf(py);
    const float wx = px - x0f,    wy = py - y0f;
    const int x0 = (int)x0f, y0 = (int)y0f;

    const bool vx0 = (x0 >= 0)  & (x0 < Wi);
    const bool vx1 = (x0 >= -1) & (x0 < Wi - 1);
    const bool vy0 = (y0 >= 0)  & (y0 < Wi);
    const bool vy1 = (y0 >= -1) & (y0 < Wi - 1);
    const float u = 1.f - wx, t = 1.f - wy;

    float c00 = (vx0 && vy0) ? p * u  * t  : 0.f;
    float c10 = (vx1 && vy0) ? p * wx * t  : 0.f;
    float c01 = (vx0 && vy1) ? p * u  * wy : 0.f;
    float c11 = (vx1 && vy1) ? p * wx * wy : 0.f;

    int idx = cur + y0 * Wi + x0;
    idx = min(max(idx, -65), NV - 1);
    const int o00 = idx << 10;

    // ---- phase 2: 8 iterations, 4 parallel (head, slot) points ----
    const int slot = (lane >> 3) & 1;
    const int c4   = lane & 7;
    const int myhead = hp * 2 + head_sel;
    const char* vb = (const char*)(v + (size_t)b * NV * EMBED + myhead * 32 + c4 * 4);
    const int srcbase = head_sel * 16 + slot;

    float a0 = 0.f, a1 = 0.f, a2 = 0.f, a3 = 0.f;
#pragma unroll
    for (int it = 0; it < 8; it++) {
        const int rowB = (64 >> (it >> 1)) << 10;
        const int src  = srcbase + it * 2;
        const int   io  = __shfl_sync(FULL, o00, src);
        const float w00 = __shfl_sync(FULL, c00, src);
        const float w10 = __shfl_sync(FULL, c10, src);
        const float w01 = __shfl_sync(FULL, c01, src);
        const float w11 = __shfl_sync(FULL, c11, src);
        const char* ad = vb + io;
        const float4 v00 = *(const float4*)(ad);
        const float4 v10 = *(const float4*)(ad + 1024);
        const float4 v01 = *(const float4*)(ad + rowB);
        const float4 v11 = *(const float4*)(ad + rowB + 1024);
        a0 = fmaf(w00, v00.x, a0); a1 = fmaf(w00, v00.y, a1);
        a2 = fmaf(w00, v00.z, a2); a3 = fmaf(w00, v00.w, a3);
        a0 = fmaf(w10, v10.x, a0); a1 = fmaf(w10, v10.y, a1);
        a2 = fmaf(w10, v10.z, a2); a3 = fmaf(w10, v10.w, a3);
        a0 = fmaf(w01, v01.x, a0); a1 = fmaf(w01, v01.y, a1);
        a2 = fmaf(w01, v01.z, a2); a3 = fmaf(w01, v01.w, a3);
        a0 = fmaf(w11, v11.x, a0); a1 = fmaf(w11, v11.y, a1);
        a2 = fmaf(w11, v11.z, a2); a3 = fmaf(w11, v11.w, a3);
    }
    a0 += __shfl_xor_sync(FULL, a0, 8);  a1 += __shfl_xor_sync(FULL, a1, 8);
    a2 += __shfl_xor_sync(FULL, a2, 8);  a3 += __shfl_xor_sync(FULL, a3, 8);

    // ---- epilogue: tf32-rounded fp32 write (slot-0 lanes of each head) ----
    if (slot == 0) {
        float4 o;
        o.x = tf32r(a0); o.y = tf32r(a1); o.z = tf32r(a2); o.w = tf32r(a3);
        *(float4*)(outs + (size_t)bq * 256 + myhead * 32 + c4 * 4) = o;
    }
}

// ---------------------------------------------------------------------------
// Launch (4 launches total)
// ---------------------------------------------------------------------------
extern "C" void kernel_launch(void* const* d_in, const int* in_sizes, int n_in,
                              void* d_out, int out_size)
{
    const float* query = (const float*)d_in[0];
    const float* value = (const float*)d_in[1];
    const float* refp  = (const float*)d_in[2];
    const float* Wv    = (const float*)d_in[3];
    const float* bv    = (const float*)d_in[4];
    const float* Wo    = (const float*)d_in[5];
    const float* bo    = (const float*)d_in[6];
    const float* Wa    = (const float*)d_in[7];
    const float* ba    = (const float*)d_in[8];
    const float* Wout  = (const float*)d_in[9];
    const float* bout  = (const float*)d_in[10];
    float* out = (float*)d_out;

    float *pvraw, *poff, *paw;
    float *pAv32, *pAq32, *pAt32, *pBv32, *pBo32, *pBa32, *pBout32;
    cudaGetSymbolAddress((void**)&pvraw,   g_vbuf);
    cudaGetSymbolAddress((void**)&poff,    g_off);
    cudaGetSymbolAddress((void**)&paw,     g_aw);
    cudaGetSymbolAddress((void**)&pAv32,   g_Av32);
    cudaGetSymbolAddress((void**)&pAq32,   g_Aq32);
    cudaGetSymbolAddress((void**)&pAt32,   g_At32);
    cudaGetSymbolAddress((void**)&pBv32,   g_Bv32);
    cudaGetSymbolAddress((void**)&pBo32,   g_Bo32);
    cudaGetSymbolAddress((void**)&pBa32,   g_Ba32);
    cudaGetSymbolAddress((void**)&pBout32, g_Bout32);
    float* pv = pvraw + VPAD;

    cudaFuncSetAttribute(gemm_fused3, cudaFuncAttributeMaxDynamicSharedMemorySize, GSMEM);
    cudaFuncSetAttribute(gemm_out,    cudaFuncAttributeMaxDynamicSharedMemorySize, GSMEM);

    conv_all<<<11776, 256>>>(value, query, Wv, Wo, Wa, Wout,
                             pAv32, pAq32, pBv32, pBo32, pBa32, pBout32);

    gemm_fused3<<<850, 256, GSMEM>>>(pAv32, pAq32, pBv32, pBo32, pBa32,
                                     bv, bo, ba, pv, poff, paw);

    msda_sample<<<MROWS / 2, 256>>>(pv, poff, paw, refp, pAt32);

    gemm_out<<<340, 256, GSMEM>>>(pAt32, pBout32, bout, out);
}